// round 10
// baseline (speedup 1.0000x reference)
#include <cuda_runtime.h>

#define BATCH 16
#define NL 3
#define NBL (BATCH * NL)
#define NBINS 1152
#define CAP 4096
#define SBUF 1024
#define ND 1000
#define SPAD(i) ((i) + ((i) >> 3))   // bank-conflict padding for u64 shared arrays

// collectA grid: single balanced wave (832 blocks <= 1184 = 148 SM x 8 blocks)
#define CH0 32768                    // floats per block, layers 0/1
#define CH2 40960                    // floats per block, layer 2
#define NB0 (BATCH * 40)             // 640
#define NB01 (NB0 + BATCH * 10)      // 800
#define NBALL (NB01 + BATCH * 2)     // 832

// ---------------- persistent scratch (zero at load; self-resetting each replay) -------
__device__ unsigned int       g_cnt[NBL];   // zeroed by sortdet at end of each replay
__device__ unsigned long long g_cand[NBL][CAP];
__device__ float              g_det[BATCH][NL][ND][7];

__constant__ float c_thr[3] = {1.0f - 3000.0f / 1310720.0f,
                               1.0f - 3000.0f / 327680.0f,
                               1.0f - 1500.0f / 81920.0f};
__constant__ int   c_K[3]      = {2000, 2000, 1024};
__constant__ int   c_shift[3]  = {6, 8, 9};   // selection histogram bin shift per layer

// Monotone bin mapping (fallback path only): fine bins over [0.5,1).
__device__ __forceinline__ int bin_of(unsigned int bits) {
    if (bits >= 0x3F800000u) return 1150;
    if (bits >= 0x3F000000u) return 126 + (int)((bits - 0x3F000000u) >> 13);
    return (int)(bits >> 23);
}

// ---------------- pass 1: single-pass collect, one balanced wave ----------------
// 4 independent coalesced LDG.128 per thread per iter; 32-reg cap, 8 blocks/SM.
// Hits staged in smem; ONE global atomic per block.
__global__ void __launch_bounds__(256, 8) collectA_kernel(const float* __restrict__ h0,
                                                          const float* __restrict__ h1,
                                                          const float* __restrict__ h2) {
    __shared__ unsigned long long s_buf[SBUF];
    __shared__ unsigned int s_cnt;
    __shared__ unsigned int s_base;

    int bid = blockIdx.x, layer, img, chunk, n, iters, celem;
    const float* heat;
    if (bid < NB0)       { layer = 0; int r = bid;        img = r / 40; chunk = r - img * 40; n = 1310720; heat = h0; celem = CH0; iters = CH0 / 4096; }
    else if (bid < NB01) { layer = 1; int r = bid - NB0;  img = r / 10; chunk = r - img * 10; n = 327680;  heat = h1; celem = CH0; iters = CH0 / 4096; }
    else                 { layer = 2; int r = bid - NB01; img = r >> 1; chunk = r & 1;        n = 81920;   heat = h2; celem = CH2; iters = CH2 / 4096; }
    int bl = img * NL + layer;
    float thr = c_thr[layer];
    unsigned int tb = __float_as_uint(thr);

    int tid = threadIdx.x;
    if (tid == 0) s_cnt = 0u;
    __syncthreads();

    const float4* p = reinterpret_cast<const float4*>(heat + (size_t)img * n) + chunk * (celem / 4);
    unsigned int base_idx = (unsigned int)chunk * (unsigned int)celem;

    for (int it = 0; it < iters; it++) {
        int i0 = it * 1024 + tid;
        float4 v[4];
#pragma unroll
        for (int u = 0; u < 4; u++) v[u] = p[i0 + u * 256];   // batched independent loads
        float mx = 0.0f;
#pragma unroll
        for (int u = 0; u < 4; u++)
            mx = fmaxf(mx, fmaxf(fmaxf(v[u].x, v[u].y), fmaxf(v[u].z, v[u].w)));
        if (mx >= thr) {   // rare
#pragma unroll
            for (int u = 0; u < 4; u++) {
                unsigned int fi = base_idx + 4u * (unsigned int)(i0 + u * 256);
                float vv[4] = {v[u].x, v[u].y, v[u].z, v[u].w};
#pragma unroll
                for (int c = 0; c < 4; c++) {
                    unsigned int bits = __float_as_uint(vv[c]);
                    if (bits >= tb) {
                        unsigned int pos = atomicAdd(&s_cnt, 1u);
                        if (pos < SBUF)
                            s_buf[pos] = ((unsigned long long)bits << 32)
                                       | (unsigned int)(~(fi + (unsigned int)c));
                    }
                }
            }
        }
    }
    __syncthreads();

    unsigned int cnt = s_cnt;
    if (cnt == 0u) return;
    if (tid == 0) {
        // local overflow: force total past CAP so the exact fallback fires
        s_base = atomicAdd(&g_cnt[bl], (cnt > SBUF) ? (CAP + 1u) : cnt);
    }
    __syncthreads();
    if (cnt > SBUF) return;

    unsigned int base = s_base;
    for (unsigned int i = tid; i < cnt; i += 256) {
        unsigned int g = base + i;
        if (g < CAP) g_cand[bl][g] = s_buf[i];
    }
}

// ---------------- register-blocked, padded bitonic sort (descending), NT threads ------
__device__ __forceinline__ void ce(unsigned long long& a, unsigned long long& b, bool dir) {
    if ((a < b) == dir) { unsigned long long t = a; a = b; b = t; }
}

template <int NT>
__device__ void bitonic_desc_opt(unsigned long long* s, int n, int tid) {
    // k = 2, 4, 8 fully in registers (8 contiguous keys per work item)
    for (int t8 = tid; t8 < (n >> 3); t8 += NT) {
        int g = t8 << 3;
        unsigned long long v[8];
#pragma unroll
        for (int x = 0; x < 8; x++) v[x] = s[SPAD(g + x)];
        ce(v[0], v[1], true);  ce(v[2], v[3], false);
        ce(v[4], v[5], true);  ce(v[6], v[7], false);
        ce(v[0], v[2], true);  ce(v[1], v[3], true);
        ce(v[4], v[6], false); ce(v[5], v[7], false);
        ce(v[0], v[1], true);  ce(v[2], v[3], true);
        ce(v[4], v[5], false); ce(v[6], v[7], false);
        bool d8 = ((g & 8) == 0);
        ce(v[0], v[4], d8); ce(v[1], v[5], d8); ce(v[2], v[6], d8); ce(v[3], v[7], d8);
        ce(v[0], v[2], d8); ce(v[1], v[3], d8); ce(v[4], v[6], d8); ce(v[5], v[7], d8);
        ce(v[0], v[1], d8); ce(v[2], v[3], d8); ce(v[4], v[5], d8); ce(v[6], v[7], d8);
#pragma unroll
        for (int x = 0; x < 8; x++) s[SPAD(g + x)] = v[x];
    }
    __syncthreads();

    for (int k = 16; k <= n; k <<= 1) {
        for (int j = k >> 1; j >= 8; j >>= 1) {
            for (int idx = tid; idx < (n >> 1); idx += NT) {
                int i = ((idx & ~(j - 1)) << 1) | (idx & (j - 1));
                int p = i + j;
                bool dir = ((i & k) == 0);
                unsigned long long a = s[SPAD(i)], b = s[SPAD(p)];
                if ((a < b) == dir) { s[SPAD(i)] = b; s[SPAD(p)] = a; }
            }
            __syncthreads();
        }
        for (int t8 = tid; t8 < (n >> 3); t8 += NT) {
            int g = t8 << 3;
            bool dir = ((g & k) == 0);
            unsigned long long v[8];
#pragma unroll
            for (int x = 0; x < 8; x++) v[x] = s[SPAD(g + x)];
            ce(v[0], v[4], dir); ce(v[1], v[5], dir); ce(v[2], v[6], dir); ce(v[3], v[7], dir);
            ce(v[0], v[2], dir); ce(v[1], v[3], dir); ce(v[4], v[6], dir); ce(v[5], v[7], dir);
            ce(v[0], v[1], dir); ce(v[2], v[3], dir); ce(v[4], v[5], dir); ce(v[6], v[7], dir);
#pragma unroll
            for (int x = 0; x < 8; x++) s[SPAD(g + x)] = v[x];
        }
        __syncthreads();
    }
}

// ---------------- pass 2: (fallback) + top-2048 selection + sort + decode -------------
__global__ void __launch_bounds__(1024) sortdet_kernel(const float* __restrict__ h0,
                                                       const float* __restrict__ h1,
                                                       const float* __restrict__ h2,
                                                       const float* __restrict__ tl0,
                                                       const float* __restrict__ br0,
                                                       const float* __restrict__ tl1,
                                                       const float* __restrict__ br1,
                                                       const float* __restrict__ tl2,
                                                       const float* __restrict__ br2) {
    __shared__ unsigned long long s[SPAD(CAP)];
    __shared__ unsigned int sh_hist[NBINS];      // reused: fallback hist / selection hist
    __shared__ unsigned int sh_tb, sh_scnt, sh_cut, sh_total;
    __shared__ int wsum[32];
    __shared__ int wtot;

    int bl = blockIdx.x, tid = threadIdx.x;
    int b = bl / NL, layer = bl % NL;

    const int   hws[3]   = {16384, 4096, 1024};
    const int   logWs[3] = {7, 6, 5};
    const float scs[3]   = {8.0f, 16.0f, 32.0f};
    int hw = hws[layer], logW = logWs[layer], K = c_K[layer];
    float scale = scs[layer];
    const float* heat = (layer == 0) ? h0 : (layer == 1) ? h1 : h2;
    const float* tl   = (layer == 0) ? tl0 : (layer == 1) ? tl1 : tl2;
    const float* br   = (layer == 0) ? br0 : (layer == 1) ? br1 : br2;
    int n_layer = 80 * hw;

    unsigned int cnt = g_cnt[bl];
    if (cnt < (unsigned int)K || cnt > CAP) {
        // -------- exact fallback, fully within this block --------
        for (int i = tid; i < NBINS; i += 1024) sh_hist[i] = 0u;
        __syncthreads();
        const float4* p = reinterpret_cast<const float4*>(heat + (size_t)b * n_layer);
        int n4 = n_layer >> 2;
        for (int i = tid; i < n4; i += 1024) {
            float4 v = p[i];
            atomicAdd(&sh_hist[bin_of(__float_as_uint(v.x))], 1u);
            atomicAdd(&sh_hist[bin_of(__float_as_uint(v.y))], 1u);
            atomicAdd(&sh_hist[bin_of(__float_as_uint(v.z))], 1u);
            atomicAdd(&sh_hist[bin_of(__float_as_uint(v.w))], 1u);
        }
        __syncthreads();
        if (tid == 0) {
            int bidx = NBINS - 1;
            unsigned int cum = 0;
            while (true) {
                cum += sh_hist[bidx];
                if (cum >= (unsigned int)K || bidx == 0) break;
                --bidx;
            }
            unsigned int lb;
            if (bidx >= 1150)     lb = 0x3F800000u;
            else if (bidx >= 126) lb = 0x3F000000u + ((unsigned int)(bidx - 126) << 13);
            else                  lb = ((unsigned int)bidx) << 23;
            sh_tb = lb;
            g_cnt[bl] = 0u;
        }
        __syncthreads();
        unsigned int tb = sh_tb;
        for (int i = tid; i < n4; i += 1024) {
            float4 v = p[i];
            unsigned int fi = 4u * (unsigned int)i;
            float vv[4] = {v.x, v.y, v.z, v.w};
#pragma unroll
            for (int c = 0; c < 4; c++) {
                unsigned int bits = __float_as_uint(vv[c]);
                if (bits >= tb) {
                    unsigned int pos = atomicAdd(&g_cnt[bl], 1u);
                    if (pos < CAP)
                        g_cand[bl][pos] = ((unsigned long long)bits << 32)
                                        | (unsigned int)(~(fi + (unsigned int)c));
                }
            }
        }
        __syncthreads();
        cnt = g_cnt[bl];
    }

    int m = (cnt > (unsigned int)CAP) ? CAP : (int)cnt;
    int nsort;

    if (m <= 2048) {
        for (int i = tid; i < 2048; i += 1024)
            s[SPAD(i)] = (i < m) ? g_cand[bl][i] : 0ull;
        nsort = 2048;
    } else {
        // ---- exact top-(<=2048) selection by value-bin histogram ----
        int shift = c_shift[layer];
        for (int i = tid; i < 1024; i += 1024) sh_hist[i] = 0u;
        __syncthreads();
        for (int i = tid; i < m; i += 1024) {
            unsigned int bits = (unsigned int)(g_cand[bl][i] >> 32);
            int off = (int)(0x3F800000u - bits);
            int bin = (off <= 0) ? 0 : min(1023, off >> shift);
            atomicAdd(&sh_hist[bin], 1u);
        }
        __syncthreads();
        // inclusive scan of sh_hist[0..1024)
        for (int off = 1; off < 1024; off <<= 1) {
            unsigned int v = sh_hist[tid & 1023];
            unsigned int a = ((tid & 1023) >= off) ? sh_hist[(tid & 1023) - off] : 0u;
            __syncthreads();
            if (tid < 1024) sh_hist[tid] = v + a;
            __syncthreads();
        }
        if (tid < 1024) {
            unsigned int cum = sh_hist[tid];
            unsigned int prev = (tid == 0) ? 0u : sh_hist[tid - 1];
            if (cum >= (unsigned int)K && prev < (unsigned int)K) {
                sh_cut = (unsigned int)tid;
                sh_total = cum;
            }
        }
        if (tid == 0) sh_scnt = 0u;
        __syncthreads();

        if (sh_total <= 2048u) {
            unsigned int cut = sh_cut;
            for (int i = tid; i < m; i += 1024) {
                unsigned long long key = g_cand[bl][i];
                unsigned int bits = (unsigned int)(key >> 32);
                int off = (int)(0x3F800000u - bits);
                unsigned int bin = (off <= 0) ? 0u : (unsigned int)min(1023, off >> shift);
                if (bin <= cut) {
                    unsigned int pos = atomicAdd(&sh_scnt, 1u);
                    s[SPAD(pos)] = key;
                }
            }
            __syncthreads();
            unsigned int tot = sh_scnt;
            for (unsigned int i = tot + tid; i < 2048u; i += 1024u) s[SPAD(i)] = 0ull;
            nsort = 2048;
        } else {
            for (int i = tid; i < CAP; i += 1024)
                s[SPAD(i)] = (i < m) ? g_cand[bl][i] : 0ull;
            nsort = CAP;
        }
    }
    __syncthreads();

    bitonic_desc_opt<1024>(s, nsort, tid);
    // s[0..K-1] = exact sorted top-K: value desc, index asc on ties.

    const float* tlp = tl + (size_t)b * 2 * hw;
    const float* brp = br + (size_t)b * 2 * hw;
    int Wm1 = (1 << logW) - 1;

    float sc_[2], d1[2], d2[2], d3[2], d4[2];
    int flag[2];
    int tsum = 0;
#pragma unroll
    for (int u = 0; u < 2; u++) {
        int r = tid * 2 + u;
        flag[u] = 0;
        if (r < K) {
            unsigned long long key = s[SPAD(r)];
            unsigned int bits = (unsigned int)(key >> 32);
            unsigned int idx  = ~(unsigned int)key;
            int sp = (int)(idx & (unsigned int)(hw - 1));
            float fy = (float)(sp >> logW);
            float fx = (float)(sp & Wm1);
            float tx = tlp[sp], ty = tlp[hw + sp];
            float bx = brp[sp], by = brp[hw + sp];
            float tlx = fx - fmaf(1.5f, tx, 2.25f);
            float tly = fy - fmaf(1.5f, ty, 2.25f);
            float brx = fx + fmaf(1.5f, bx, 2.25f);
            float bry = fy + fmaf(1.5f, by, 2.25f);
            bool valid = !((brx < tlx) || (bry < tly));
            flag[u] = valid ? 1 : 0;
            sc_[u] = valid ? __uint_as_float(bits) : -1.0f;
            d1[u] = tlx * scale; d2[u] = tly * scale;
            d3[u] = brx * scale; d4[u] = bry * scale;
            tsum += flag[u];
        }
    }

    // block exclusive scan of valid flags (thread t owns ranks 2t, 2t+1)
    int lane = tid & 31, warp = tid >> 5;
    int incl = tsum;
#pragma unroll
    for (int off = 1; off < 32; off <<= 1) {
        int t2 = __shfl_up_sync(0xffffffffu, incl, off);
        if (lane >= off) incl += t2;
    }
    if (lane == 31) wsum[warp] = incl;
    __syncthreads();
    if (tid < 32) {
        int v = wsum[tid];
#pragma unroll
        for (int off = 1; off < 32; off <<= 1) {
            int t2 = __shfl_up_sync(0xffffffffu, v, off);
            if (lane >= off) v += t2;
        }
        wsum[tid] = v;
        if (tid == 31) wtot = v;
    }
    __syncthreads();

    int total_valid = wtot;
    int run = (warp ? wsum[warp - 1] : 0) + (incl - tsum);
#pragma unroll
    for (int u = 0; u < 2; u++) {
        int r = tid * 2 + u;
        if (r < K) {
            int pos = flag[u] ? run : (total_valid + (r - run));
            if (pos < ND) {
                float* d = g_det[b][layer][pos];
                d[0] = sc_[u]; d[1] = d1[u]; d[2] = d2[u];
                d[3] = d3[u];  d[4] = d4[u]; d[5] = 0.0f; d[6] = 0.0f;
            }
            run += flag[u];
        }
    }
    __syncthreads();
    if (tid < 7) g_det[b][layer][6][tid] = (float)layer;   // det.at[:,6,:] = layer
    if (tid == 0) g_cnt[bl] = 0u;                          // reset for next replay
}

// ---------------- pass 3: 3-way sorted merge by ranking (no sort) ----------------
__global__ void __launch_bounds__(1024) final_kernel(float* __restrict__ out) {
    __shared__ unsigned long long keys[NL * ND];
    __shared__ unsigned long long ovk[NL];
    int b = blockIdx.x, tid = threadIdx.x;

    for (int i = tid; i < NL * ND; i += 1024) {
        int l = i / ND, r = i - l * ND;
        unsigned int sb = __float_as_uint(g_det[b][l][r][0]);
        unsigned int mp = (sb & 0x80000000u) ? ~sb : (sb | 0x80000000u);  // monotone map
        keys[i] = ((unsigned long long)mp << 32) | (unsigned int)(~(unsigned int)i);
    }
    __syncthreads();
    if (tid < NL) ovk[tid] = keys[tid * ND + 6];
    __syncthreads();

    for (int e = tid; e < NL * ND; e += 1024) {
        unsigned long long my = keys[e];
        int rank = 0;
#pragma unroll
        for (int l = 0; l < NL; l++) {
            // count strictly greater in holed (999-elem) descending list of segment l
            int lo = 0, hi = ND - 1;
            int base = l * ND;
            while (lo < hi) {
                int mid = (lo + hi) >> 1;
                int ph = mid + (mid >= 6);
                if (keys[base + ph] > my) lo = mid + 1; else hi = mid;
            }
            rank += lo + (ovk[l] > my ? 1 : 0);
        }
        if (rank < ND) {
            int l = e / ND, r = e - l * ND;
            const float* src = g_det[b][l][r];
            float* dst = out + ((size_t)b * ND + rank) * 7;
#pragma unroll
            for (int c = 0; c < 7; c++) dst[c] = src[c];
        }
    }
}

extern "C" void kernel_launch(void* const* d_in, const int* in_sizes, int n_in,
                              void* d_out, int out_size) {
    const int hw[3] = {16384, 4096, 1024};

    // Resolve inputs BY SIZE (metadata order is heat0, tl0, br0, heat1, ...).
    const float* heat[3] = {0, 0, 0};
    const float* tl[3]   = {0, 0, 0};
    const float* br[3]   = {0, 0, 0};
    for (int i = 0; i < n_in; i++) {
        long long sz = in_sizes[i];
        for (int l = 0; l < 3; l++) {
            if (sz == (long long)BATCH * 80 * hw[l]) {
                heat[l] = (const float*)d_in[i];
            } else if (sz == (long long)BATCH * 2 * hw[l]) {
                if (!tl[l]) tl[l] = (const float*)d_in[i];
                else        br[l] = (const float*)d_in[i];
            }
        }
    }

    collectA_kernel<<<NBALL, 256>>>(heat[0], heat[1], heat[2]);
    sortdet_kernel<<<NBL, 1024>>>(heat[0], heat[1], heat[2],
                                  tl[0], br[0], tl[1], br[1], tl[2], br[2]);
    final_kernel<<<BATCH, 1024>>>((float*)d_out);
}

// round 11
// speedup vs baseline: 1.0423x; 1.0423x over previous
#include <cuda_runtime.h>

#define BATCH 16
#define NL 3
#define NBL (BATCH * NL)
#define NBINS 1152
#define CAP 4096
#define SBUF 512
#define ND 1000
#define CHUNK 16384
#define SPAD(i) ((i) + ((i) >> 3))   // bank-conflict padding for u64 shared arrays

// grid layout for collectA (per-layer chunk counts) — R9 config (proven best)
#define BPI0 80
#define BPI1 20
#define BPI2 5
#define BLK0 (BATCH * BPI0)              // 1280
#define BLK01 (BLK0 + BATCH * BPI1)      // 1600
#define BLKALL (BLK01 + BATCH * BPI2)    // 1680

// ---------------- persistent scratch (zero at load; self-resetting each replay) -------
__device__ unsigned int       g_cnt[NBL];     // zeroed by sortdet at end of each replay
__device__ unsigned int       g_batch[BATCH]; // per-batch arrival counter; reset by merger
__device__ unsigned long long g_cand[NBL][CAP];
__device__ float              g_det[BATCH][NL][ND][7];

__constant__ float c_thr[3] = {1.0f - 3000.0f / 1310720.0f,
                               1.0f - 3000.0f / 327680.0f,
                               1.0f - 1500.0f / 81920.0f};
__constant__ int   c_K[3]      = {2000, 2000, 1024};
__constant__ int   c_shift[3]  = {6, 8, 9};   // selection histogram bin shift per layer

// Monotone bin mapping (fallback path only): fine bins over [0.5,1).
__device__ __forceinline__ int bin_of(unsigned int bits) {
    if (bits >= 0x3F800000u) return 1150;
    if (bits >= 0x3F000000u) return 126 + (int)((bits - 0x3F000000u) >> 13);
    return (int)(bits >> 23);
}

// ---------------- pass 1: single-pass collect with static thresholds (R9) -------------
__global__ void __launch_bounds__(256, 8) collectA_kernel(const float* __restrict__ h0,
                                                          const float* __restrict__ h1,
                                                          const float* __restrict__ h2) {
    __shared__ unsigned long long s_buf[SBUF];
    __shared__ unsigned int s_cnt;
    __shared__ unsigned int s_base;

    int bid = blockIdx.x, layer, img, chunk, n;
    const float* heat;
    if (bid < BLK0)       { layer = 0; int r = bid;         img = r / BPI0; chunk = r - img * BPI0; n = 80 * 16384; heat = h0; }
    else if (bid < BLK01) { layer = 1; int r = bid - BLK0;  img = r / BPI1; chunk = r - img * BPI1; n = 80 * 4096;  heat = h1; }
    else                  { layer = 2; int r = bid - BLK01; img = r / BPI2; chunk = r - img * BPI2; n = 80 * 1024;  heat = h2; }
    int bl = img * NL + layer;
    float thr = c_thr[layer];
    unsigned int tb = __float_as_uint(thr);

    int tid = threadIdx.x;
    if (tid == 0) s_cnt = 0u;
    __syncthreads();

    const float4* p = reinterpret_cast<const float4*>(heat + (size_t)img * n) + chunk * (CHUNK / 4);
    unsigned int base_idx = (unsigned int)chunk * CHUNK;

    // CHUNK/4 = 4096 float4 = 4 outer iters × 4 unrolled × 256 threads
#pragma unroll
    for (int it = 0; it < 4; it++) {
        int i0 = it * 1024 + tid;
        float4 v[4];
#pragma unroll
        for (int u = 0; u < 4; u++) v[u] = p[i0 + u * 256];   // batched independent loads
        float mx = 0.0f;
#pragma unroll
        for (int u = 0; u < 4; u++)
            mx = fmaxf(mx, fmaxf(fmaxf(v[u].x, v[u].y), fmaxf(v[u].z, v[u].w)));
        if (mx >= thr) {   // rare (~1% of threads)
#pragma unroll
            for (int u = 0; u < 4; u++) {
                unsigned int fi = base_idx + 4u * (unsigned int)(i0 + u * 256);
                float vv[4] = {v[u].x, v[u].y, v[u].z, v[u].w};
#pragma unroll
                for (int c = 0; c < 4; c++) {
                    unsigned int bits = __float_as_uint(vv[c]);
                    if (bits >= tb) {
                        unsigned int pos = atomicAdd(&s_cnt, 1u);
                        if (pos < SBUF)
                            s_buf[pos] = ((unsigned long long)bits << 32)
                                       | (unsigned int)(~(fi + (unsigned int)c));
                    }
                }
            }
        }
    }
    __syncthreads();

    unsigned int cnt = s_cnt;
    if (cnt == 0u) return;
    if (tid == 0) {
        // local overflow: force total past CAP so the exact fallback fires
        s_base = atomicAdd(&g_cnt[bl], (cnt > SBUF) ? (CAP + 1u) : cnt);
    }
    __syncthreads();
    if (cnt > SBUF) return;

    unsigned int base = s_base;
    for (unsigned int i = tid; i < cnt; i += 256) {
        unsigned int g = base + i;
        if (g < CAP) g_cand[bl][g] = s_buf[i];
    }
}

// ---------------- register-blocked, padded bitonic sort (descending), NT threads ------
__device__ __forceinline__ void ce(unsigned long long& a, unsigned long long& b, bool dir) {
    if ((a < b) == dir) { unsigned long long t = a; a = b; b = t; }
}

template <int NT>
__device__ void bitonic_desc_opt(unsigned long long* s, int n, int tid) {
    // k = 2, 4, 8 fully in registers (8 contiguous keys per work item)
    for (int t8 = tid; t8 < (n >> 3); t8 += NT) {
        int g = t8 << 3;
        unsigned long long v[8];
#pragma unroll
        for (int x = 0; x < 8; x++) v[x] = s[SPAD(g + x)];
        ce(v[0], v[1], true);  ce(v[2], v[3], false);
        ce(v[4], v[5], true);  ce(v[6], v[7], false);
        ce(v[0], v[2], true);  ce(v[1], v[3], true);
        ce(v[4], v[6], false); ce(v[5], v[7], false);
        ce(v[0], v[1], true);  ce(v[2], v[3], true);
        ce(v[4], v[5], false); ce(v[6], v[7], false);
        bool d8 = ((g & 8) == 0);
        ce(v[0], v[4], d8); ce(v[1], v[5], d8); ce(v[2], v[6], d8); ce(v[3], v[7], d8);
        ce(v[0], v[2], d8); ce(v[1], v[3], d8); ce(v[4], v[6], d8); ce(v[5], v[7], d8);
        ce(v[0], v[1], d8); ce(v[2], v[3], d8); ce(v[4], v[5], d8); ce(v[6], v[7], d8);
#pragma unroll
        for (int x = 0; x < 8; x++) s[SPAD(g + x)] = v[x];
    }
    __syncthreads();

    for (int k = 16; k <= n; k <<= 1) {
        for (int j = k >> 1; j >= 8; j >>= 1) {
            for (int idx = tid; idx < (n >> 1); idx += NT) {
                int i = ((idx & ~(j - 1)) << 1) | (idx & (j - 1));
                int p = i + j;
                bool dir = ((i & k) == 0);
                unsigned long long a = s[SPAD(i)], b = s[SPAD(p)];
                if ((a < b) == dir) { s[SPAD(i)] = b; s[SPAD(p)] = a; }
            }
            __syncthreads();
        }
        for (int t8 = tid; t8 < (n >> 3); t8 += NT) {
            int g = t8 << 3;
            bool dir = ((g & k) == 0);
            unsigned long long v[8];
#pragma unroll
            for (int x = 0; x < 8; x++) v[x] = s[SPAD(g + x)];
            ce(v[0], v[4], dir); ce(v[1], v[5], dir); ce(v[2], v[6], dir); ce(v[3], v[7], dir);
            ce(v[0], v[2], dir); ce(v[1], v[3], dir); ce(v[4], v[6], dir); ce(v[5], v[7], dir);
            ce(v[0], v[1], dir); ce(v[2], v[3], dir); ce(v[4], v[5], dir); ce(v[6], v[7], dir);
#pragma unroll
            for (int x = 0; x < 8; x++) s[SPAD(g + x)] = v[x];
        }
        __syncthreads();
    }
}

// ---- pass 2: (fallback) + top-2048 selection + sort + decode + FUSED final merge -----
__global__ void __launch_bounds__(1024) sortdet_kernel(const float* __restrict__ h0,
                                                       const float* __restrict__ h1,
                                                       const float* __restrict__ h2,
                                                       const float* __restrict__ tl0,
                                                       const float* __restrict__ br0,
                                                       const float* __restrict__ tl1,
                                                       const float* __restrict__ br1,
                                                       const float* __restrict__ tl2,
                                                       const float* __restrict__ br2,
                                                       float* __restrict__ out) {
    __shared__ unsigned long long s[SPAD(CAP)];  // sort buffer; reused as merge key array
    __shared__ unsigned int sh_hist[NBINS];      // fallback hist / selection hist
    __shared__ unsigned int sh_tb, sh_scnt, sh_cut, sh_total;
    __shared__ int wsum[32];
    __shared__ int wtot;
    __shared__ int sh_last;
    __shared__ unsigned long long ovk[NL];

    int bl = blockIdx.x, tid = threadIdx.x;
    int b = bl / NL, layer = bl % NL;

    const int   hws[3]   = {16384, 4096, 1024};
    const int   logWs[3] = {7, 6, 5};
    const float scs[3]   = {8.0f, 16.0f, 32.0f};
    int hw = hws[layer], logW = logWs[layer], K = c_K[layer];
    float scale = scs[layer];
    const float* heat = (layer == 0) ? h0 : (layer == 1) ? h1 : h2;
    const float* tl   = (layer == 0) ? tl0 : (layer == 1) ? tl1 : tl2;
    const float* br   = (layer == 0) ? br0 : (layer == 1) ? br1 : br2;
    int n_layer = 80 * hw;

    unsigned int cnt = g_cnt[bl];
    if (cnt < (unsigned int)K || cnt > CAP) {
        // -------- exact fallback, fully within this block --------
        for (int i = tid; i < NBINS; i += 1024) sh_hist[i] = 0u;
        __syncthreads();
        const float4* p = reinterpret_cast<const float4*>(heat + (size_t)b * n_layer);
        int n4 = n_layer >> 2;
        for (int i = tid; i < n4; i += 1024) {
            float4 v = p[i];
            atomicAdd(&sh_hist[bin_of(__float_as_uint(v.x))], 1u);
            atomicAdd(&sh_hist[bin_of(__float_as_uint(v.y))], 1u);
            atomicAdd(&sh_hist[bin_of(__float_as_uint(v.z))], 1u);
            atomicAdd(&sh_hist[bin_of(__float_as_uint(v.w))], 1u);
        }
        __syncthreads();
        if (tid == 0) {
            int bidx = NBINS - 1;
            unsigned int cum = 0;
            while (true) {
                cum += sh_hist[bidx];
                if (cum >= (unsigned int)K || bidx == 0) break;
                --bidx;
            }
            unsigned int lb;
            if (bidx >= 1150)     lb = 0x3F800000u;
            else if (bidx >= 126) lb = 0x3F000000u + ((unsigned int)(bidx - 126) << 13);
            else                  lb = ((unsigned int)bidx) << 23;
            sh_tb = lb;
            g_cnt[bl] = 0u;
        }
        __syncthreads();
        unsigned int tb = sh_tb;
        for (int i = tid; i < n4; i += 1024) {
            float4 v = p[i];
            unsigned int fi = 4u * (unsigned int)i;
            float vv[4] = {v.x, v.y, v.z, v.w};
#pragma unroll
            for (int c = 0; c < 4; c++) {
                unsigned int bits = __float_as_uint(vv[c]);
                if (bits >= tb) {
                    unsigned int pos = atomicAdd(&g_cnt[bl], 1u);
                    if (pos < CAP)
                        g_cand[bl][pos] = ((unsigned long long)bits << 32)
                                        | (unsigned int)(~(fi + (unsigned int)c));
                }
            }
        }
        __syncthreads();
        cnt = g_cnt[bl];
    }

    int m = (cnt > (unsigned int)CAP) ? CAP : (int)cnt;
    int nsort;

    if (m <= 2048) {
        for (int i = tid; i < 2048; i += 1024)
            s[SPAD(i)] = (i < m) ? g_cand[bl][i] : 0ull;
        nsort = 2048;
    } else {
        // ---- exact top-(<=2048) selection by value-bin histogram ----
        int shift = c_shift[layer];
        if (tid < 1024) sh_hist[tid] = 0u;
        __syncthreads();
        for (int i = tid; i < m; i += 1024) {
            unsigned int bits = (unsigned int)(g_cand[bl][i] >> 32);
            int off = (int)(0x3F800000u - bits);
            int bin = (off <= 0) ? 0 : min(1023, off >> shift);
            atomicAdd(&sh_hist[bin], 1u);
        }
        __syncthreads();
        // inclusive scan of sh_hist[0..1024)
        for (int off = 1; off < 1024; off <<= 1) {
            unsigned int v = sh_hist[tid & 1023];
            unsigned int a = ((tid & 1023) >= off) ? sh_hist[(tid & 1023) - off] : 0u;
            __syncthreads();
            if (tid < 1024) sh_hist[tid] = v + a;
            __syncthreads();
        }
        if (tid < 1024) {
            unsigned int cum = sh_hist[tid];
            unsigned int prev = (tid == 0) ? 0u : sh_hist[tid - 1];
            if (cum >= (unsigned int)K && prev < (unsigned int)K) {
                sh_cut = (unsigned int)tid;
                sh_total = cum;
            }
        }
        if (tid == 0) sh_scnt = 0u;
        __syncthreads();

        if (sh_total <= 2048u) {
            unsigned int cut = sh_cut;
            for (int i = tid; i < m; i += 1024) {
                unsigned long long key = g_cand[bl][i];
                unsigned int bits = (unsigned int)(key >> 32);
                int off = (int)(0x3F800000u - bits);
                unsigned int bin = (off <= 0) ? 0u : (unsigned int)min(1023, off >> shift);
                if (bin <= cut) {
                    unsigned int pos = atomicAdd(&sh_scnt, 1u);
                    s[SPAD(pos)] = key;
                }
            }
            __syncthreads();
            unsigned int tot = sh_scnt;
            for (unsigned int i = tot + tid; i < 2048u; i += 1024u) s[SPAD(i)] = 0ull;
            nsort = 2048;
        } else {
            for (int i = tid; i < CAP; i += 1024)
                s[SPAD(i)] = (i < m) ? g_cand[bl][i] : 0ull;
            nsort = CAP;
        }
    }
    __syncthreads();

    bitonic_desc_opt<1024>(s, nsort, tid);
    // s[0..K-1] = exact sorted top-K: value desc, index asc on ties.

    const float* tlp = tl + (size_t)b * 2 * hw;
    const float* brp = br + (size_t)b * 2 * hw;
    int Wm1 = (1 << logW) - 1;

    float sc_[2], d1[2], d2[2], d3[2], d4[2];
    int flag[2];
    int tsum = 0;
#pragma unroll
    for (int u = 0; u < 2; u++) {
        int r = tid * 2 + u;
        flag[u] = 0;
        if (r < K) {
            unsigned long long key = s[SPAD(r)];
            unsigned int bits = (unsigned int)(key >> 32);
            unsigned int idx  = ~(unsigned int)key;
            int sp = (int)(idx & (unsigned int)(hw - 1));
            float fy = (float)(sp >> logW);
            float fx = (float)(sp & Wm1);
            float tx = tlp[sp], ty = tlp[hw + sp];
            float bx = brp[sp], by = brp[hw + sp];
            float tlx = fx - fmaf(1.5f, tx, 2.25f);
            float tly = fy - fmaf(1.5f, ty, 2.25f);
            float brx = fx + fmaf(1.5f, bx, 2.25f);
            float bry = fy + fmaf(1.5f, by, 2.25f);
            bool valid = !((brx < tlx) || (bry < tly));
            flag[u] = valid ? 1 : 0;
            sc_[u] = valid ? __uint_as_float(bits) : -1.0f;
            d1[u] = tlx * scale; d2[u] = tly * scale;
            d3[u] = brx * scale; d4[u] = bry * scale;
            tsum += flag[u];
        }
    }

    // block exclusive scan of valid flags (thread t owns ranks 2t, 2t+1)
    int lane = tid & 31, warp = tid >> 5;
    int incl = tsum;
#pragma unroll
    for (int off = 1; off < 32; off <<= 1) {
        int t2 = __shfl_up_sync(0xffffffffu, incl, off);
        if (lane >= off) incl += t2;
    }
    if (lane == 31) wsum[warp] = incl;
    __syncthreads();
    if (tid < 32) {
        int v = wsum[tid];
#pragma unroll
        for (int off = 1; off < 32; off <<= 1) {
            int t2 = __shfl_up_sync(0xffffffffu, v, off);
            if (lane >= off) v += t2;
        }
        wsum[tid] = v;
        if (tid == 31) wtot = v;
    }
    __syncthreads();

    int total_valid = wtot;
    int run = (warp ? wsum[warp - 1] : 0) + (incl - tsum);
#pragma unroll
    for (int u = 0; u < 2; u++) {
        int r = tid * 2 + u;
        if (r < K) {
            int pos = flag[u] ? run : (total_valid + (r - run));
            if (pos < ND) {
                float* d = g_det[b][layer][pos];
                d[0] = sc_[u]; d[1] = d1[u]; d[2] = d2[u];
                d[3] = d3[u];  d[4] = d4[u]; d[5] = 0.0f; d[6] = 0.0f;
            }
            run += flag[u];
        }
    }
    __syncthreads();
    if (tid < 7) g_det[b][layer][6][tid] = (float)layer;   // det.at[:,6,:] = layer
    if (tid == 0) g_cnt[bl] = 0u;                          // reset for next replay
    __syncthreads();

    // ---------------- fused final merge: third arriver of batch b does it -------------
    __threadfence();                                       // release g_det writes
    if (tid == 0) {
        unsigned int prev = atomicAdd(&g_batch[b], 1u);
        sh_last = (prev == 2u);
    }
    __syncthreads();
    if (!sh_last) return;
    __threadfence();                                       // acquire peers' g_det writes

    // build keys (reuse s, unpadded: 4608 slots >= 3000)
    for (int i = tid; i < NL * ND; i += 1024) {
        int l = i / ND, r = i - l * ND;
        unsigned int sb = __float_as_uint(g_det[b][l][r][0]);
        unsigned int mp = (sb & 0x80000000u) ? ~sb : (sb | 0x80000000u);  // monotone map
        s[i] = ((unsigned long long)mp << 32) | (unsigned int)(~(unsigned int)i);
    }
    __syncthreads();
    if (tid < NL) ovk[tid] = s[tid * ND + 6];
    __syncthreads();

    for (int e = tid; e < NL * ND; e += 1024) {
        unsigned long long my = s[e];
        int rank = 0;
#pragma unroll
        for (int l = 0; l < NL; l++) {
            // count strictly greater in holed (999-elem) descending list of segment l
            int lo = 0, hi = ND - 1;
            int base = l * ND;
            while (lo < hi) {
                int mid = (lo + hi) >> 1;
                int ph = mid + (mid >= 6);
                if (s[base + ph] > my) lo = mid + 1; else hi = mid;
            }
            rank += lo + (ovk[l] > my ? 1 : 0);
        }
        if (rank < ND) {
            int l = e / ND, r = e - l * ND;
            const float* src = g_det[b][l][r];
            float* dst = out + ((size_t)b * ND + rank) * 7;
#pragma unroll
            for (int c = 0; c < 7; c++) dst[c] = src[c];
        }
    }
    __syncthreads();
    if (tid == 0) g_batch[b] = 0u;                        // reset for next replay
}

extern "C" void kernel_launch(void* const* d_in, const int* in_sizes, int n_in,
                              void* d_out, int out_size) {
    const int hw[3] = {16384, 4096, 1024};

    // Resolve inputs BY SIZE (metadata order is heat0, tl0, br0, heat1, ...).
    const float* heat[3] = {0, 0, 0};
    const float* tl[3]   = {0, 0, 0};
    const float* br[3]   = {0, 0, 0};
    for (int i = 0; i < n_in; i++) {
        long long sz = in_sizes[i];
        for (int l = 0; l < 3; l++) {
            if (sz == (long long)BATCH * 80 * hw[l]) {
                heat[l] = (const float*)d_in[i];
            } else if (sz == (long long)BATCH * 2 * hw[l]) {
                if (!tl[l]) tl[l] = (const float*)d_in[i];
                else        br[l] = (const float*)d_in[i];
            }
        }
    }

    collectA_kernel<<<BLKALL, 256>>>(heat[0], heat[1], heat[2]);
    sortdet_kernel<<<NBL, 1024>>>(heat[0], heat[1], heat[2],
                                  tl[0], br[0], tl[1], br[1], tl[2], br[2],
                                  (float*)d_out);
}